// round 6
// baseline (speedup 1.0000x reference)
#include <cuda_runtime.h>
#include <cuda_bf16.h>

#define NROWS 8192
#define DDIM  256
#define BM 128
#define BN 128
#define BK 16

// Scratch (no cudaMalloc allowed): normalized copy of X + per-row accumulators.
__device__ float g_Y[NROWS * DDIM];
__device__ float g_tot[NROWS];
__device__ float g_pos[NROWS];

// ---------------------------------------------------------------------------
// Kernel 1: normalize rows (one warp per row) + zero accumulators.
// ---------------------------------------------------------------------------
__global__ void norm_kernel(const float* __restrict__ X) {
    int row  = blockIdx.x * 8 + (threadIdx.x >> 5);
    int lane = threadIdx.x & 31;
    const float4* x4 = reinterpret_cast<const float4*>(X + row * DDIM);
    float4 v1 = x4[lane];
    float4 v2 = x4[lane + 32];
    float ss = v1.x * v1.x + v1.y * v1.y + v1.z * v1.z + v1.w * v1.w
             + v2.x * v2.x + v2.y * v2.y + v2.z * v2.z + v2.w * v2.w;
    #pragma unroll
    for (int o = 16; o > 0; o >>= 1) ss += __shfl_xor_sync(0xffffffffu, ss, o);
    float rinv = rsqrtf(ss);
    float4* y4 = reinterpret_cast<float4*>(g_Y + row * DDIM);
    v1.x *= rinv; v1.y *= rinv; v1.z *= rinv; v1.w *= rinv;
    v2.x *= rinv; v2.y *= rinv; v2.z *= rinv; v2.w *= rinv;
    y4[lane]      = v1;
    y4[lane + 32] = v2;
    if (lane == 0) { g_tot[row] = 0.0f; g_pos[row] = 0.0f; }
}

// ---------------------------------------------------------------------------
// Kernel 2: fused 128x128x256 NT-SGEMM tile + exp epilogue + row accumulation.
// Thread layout: 16x16 threads, each owns an 8x8 micro-tile split as
// rows {ty*4..+3, 64+ty*4..+3} x cols {tx*4..+3, 64+tx*4..+3}.
// ---------------------------------------------------------------------------
__global__ __launch_bounds__(256, 2)
void gemm_fused_kernel(const int* __restrict__ labels,
                       const float* __restrict__ tptr) {
    __shared__ float As[2][BK][BM];
    __shared__ float Bs[2][BK][BN];
    __shared__ int   lr[BM];
    __shared__ int   lc[BN];

    const int tid = threadIdx.x;
    const int tx  = tid & 15;
    const int ty  = tid >> 4;
    const int row0 = blockIdx.y * BM;
    const int col0 = blockIdx.x * BN;

    if (tid < 128) lr[tid] = labels[row0 + tid];
    else           lc[tid - 128] = labels[col0 + tid - 128];

    const float4* A4 = reinterpret_cast<const float4*>(g_Y + row0 * DDIM);
    const float4* B4 = reinterpret_cast<const float4*>(g_Y + col0 * DDIM);

    // Per-thread global-load slots: float4 index f in {tid, tid+256};
    // r = f/4 (tile row), q = f%4 (float4 within the 16-float K chunk).
    const int r_a = tid >> 2;
    const int q_a = tid & 3;

    float acc[8][8];
    #pragma unroll
    for (int m = 0; m < 8; m++)
        #pragma unroll
        for (int n = 0; n < 8; n++) acc[m][n] = 0.0f;

    // Preload tile 0
    {
        float4 a0 = A4[r_a * 64 + q_a];
        float4 a1 = A4[(r_a + 64) * 64 + q_a];
        float4 b0 = B4[r_a * 64 + q_a];
        float4 b1 = B4[(r_a + 64) * 64 + q_a];
        As[0][q_a * 4 + 0][r_a] = a0.x; As[0][q_a * 4 + 1][r_a] = a0.y;
        As[0][q_a * 4 + 2][r_a] = a0.z; As[0][q_a * 4 + 3][r_a] = a0.w;
        As[0][q_a * 4 + 0][r_a + 64] = a1.x; As[0][q_a * 4 + 1][r_a + 64] = a1.y;
        As[0][q_a * 4 + 2][r_a + 64] = a1.z; As[0][q_a * 4 + 3][r_a + 64] = a1.w;
        Bs[0][q_a * 4 + 0][r_a] = b0.x; Bs[0][q_a * 4 + 1][r_a] = b0.y;
        Bs[0][q_a * 4 + 2][r_a] = b0.z; Bs[0][q_a * 4 + 3][r_a] = b0.w;
        Bs[0][q_a * 4 + 0][r_a + 64] = b1.x; Bs[0][q_a * 4 + 1][r_a + 64] = b1.y;
        Bs[0][q_a * 4 + 2][r_a + 64] = b1.z; Bs[0][q_a * 4 + 3][r_a + 64] = b1.w;
    }
    __syncthreads();

    int buf = 0;
    const int NT = DDIM / BK;  // 16 k-tiles
    #pragma unroll 1
    for (int kt = 0; kt < NT; kt++) {
        float4 na0, na1, nb0, nb1;
        if (kt < NT - 1) {
            int kof = (kt + 1) * 4;
            na0 = A4[r_a * 64 + kof + q_a];
            na1 = A4[(r_a + 64) * 64 + kof + q_a];
            nb0 = B4[r_a * 64 + kof + q_a];
            nb1 = B4[(r_a + 64) * 64 + kof + q_a];
        }
        #pragma unroll
        for (int k = 0; k < BK; k++) {
            float4 af0 = *reinterpret_cast<const float4*>(&As[buf][k][ty * 4]);
            float4 af1 = *reinterpret_cast<const float4*>(&As[buf][k][64 + ty * 4]);
            float4 bf0 = *reinterpret_cast<const float4*>(&Bs[buf][k][tx * 4]);
            float4 bf1 = *reinterpret_cast<const float4*>(&Bs[buf][k][64 + tx * 4]);
            float a[8] = {af0.x, af0.y, af0.z, af0.w, af1.x, af1.y, af1.z, af1.w};
            float b[8] = {bf0.x, bf0.y, bf0.z, bf0.w, bf1.x, bf1.y, bf1.z, bf1.w};
            #pragma unroll
            for (int m = 0; m < 8; m++)
                #pragma unroll
                for (int n = 0; n < 8; n++)
                    acc[m][n] = fmaf(a[m], b[n], acc[m][n]);
        }
        if (kt < NT - 1) {
            buf ^= 1;
            As[buf][q_a * 4 + 0][r_a] = na0.x; As[buf][q_a * 4 + 1][r_a] = na0.y;
            As[buf][q_a * 4 + 2][r_a] = na0.z; As[buf][q_a * 4 + 3][r_a] = na0.w;
            As[buf][q_a * 4 + 0][r_a + 64] = na1.x; As[buf][q_a * 4 + 1][r_a + 64] = na1.y;
            As[buf][q_a * 4 + 2][r_a + 64] = na1.z; As[buf][q_a * 4 + 3][r_a + 64] = na1.w;
            Bs[buf][q_a * 4 + 0][r_a] = nb0.x; Bs[buf][q_a * 4 + 1][r_a] = nb0.y;
            Bs[buf][q_a * 4 + 2][r_a] = nb0.z; Bs[buf][q_a * 4 + 3][r_a] = nb0.w;
            Bs[buf][q_a * 4 + 0][r_a + 64] = nb1.x; Bs[buf][q_a * 4 + 1][r_a + 64] = nb1.y;
            Bs[buf][q_a * 4 + 2][r_a + 64] = nb1.z; Bs[buf][q_a * 4 + 3][r_a + 64] = nb1.w;
            __syncthreads();
        }
    }

    // ---- Epilogue: e = exp(cos/t); tot += e; pos += (same label ? e : 1) ----
    const float invT = 1.0f / (*tptr);   // cos/t ; __expf handles the rest

    int rl[8], cl[8], rix[8];
    #pragma unroll
    for (int m = 0; m < 8; m++) {
        int rm = (m < 4) ? (ty * 4 + m) : (64 + ty * 4 + m - 4);
        rix[m] = rm;
        rl[m]  = lr[rm];
    }
    #pragma unroll
    for (int n = 0; n < 8; n++) {
        int cn = (n < 4) ? (tx * 4 + n) : (64 + tx * 4 + n - 4);
        cl[n] = lc[cn];
    }

    #pragma unroll
    for (int m = 0; m < 8; m++) {
        float ts = 0.0f, ps = 0.0f;
        #pragma unroll
        for (int n = 0; n < 8; n++) {
            float e = __expf(acc[m][n] * invT);
            ts += e;
            ps += (rl[m] == cl[n]) ? e : 1.0f;
        }
        // Reduce across tx (lanes 0..15 / 16..31 hold the same rows)
        #pragma unroll
        for (int o = 8; o > 0; o >>= 1) {
            ts += __shfl_xor_sync(0xffffffffu, ts, o);
            ps += __shfl_xor_sync(0xffffffffu, ps, o);
        }
        if (tx == 0) {
            atomicAdd(&g_tot[row0 + rix[m]], ts);
            atomicAdd(&g_pos[row0 + rix[m]], ps);
        }
    }
}

// ---------------------------------------------------------------------------
// Kernel 3: loss = sum_i [log(tot_i + N - pos_i) - log(pos_i)] / N
// ---------------------------------------------------------------------------
__global__ void loss_kernel(float* __restrict__ out) {
    __shared__ double sd[256];
    double a = 0.0;
    for (int r = threadIdx.x; r < NROWS; r += 256) {
        float p  = g_pos[r];
        float ng = g_tot[r] + (float)NROWS - p;
        a += (double)(logf(ng) - logf(p));
    }
    sd[threadIdx.x] = a;
    __syncthreads();
    #pragma unroll
    for (int o = 128; o > 0; o >>= 1) {
        if (threadIdx.x < o) sd[threadIdx.x] += sd[threadIdx.x + o];
        __syncthreads();
    }
    if (threadIdx.x == 0) out[0] = (float)(sd[0] / (double)NROWS);
}

// ---------------------------------------------------------------------------
extern "C" void kernel_launch(void* const* d_in, const int* in_sizes, int n_in,
                              void* d_out, int out_size) {
    const float* X   = (const float*)d_in[0];
    const int*   lab = (const int*)d_in[1];
    const float* t   = (const float*)d_in[2];
    float*       out = (float*)d_out;

    norm_kernel<<<NROWS / 8, 256>>>(X);
    dim3 grid(NROWS / BN, NROWS / BM);
    gemm_fused_kernel<<<grid, 256>>>(lab, t);
    loss_kernel<<<1, 256>>>(out);
}

// round 8
// speedup vs baseline: 2.4400x; 2.4400x over previous
#include <cuda_runtime.h>
#include <cuda_bf16.h>
#include <cstdint>

#define NROWS 8192
#define DDIM  256
#define TM    128
#define TN    128
#define KCH   64            // K chunk in bf16 elems = 128 bytes/row

// Scratch (no cudaMalloc allowed).
__device__ __nv_bfloat16 g_Yhi[NROWS * DDIM];
__device__ __nv_bfloat16 g_Ylo[NROWS * DDIM];
__device__ float g_tot[NROWS];
__device__ float g_pos[NROWS];

// SMEM per buffer: Ahi 16K | Alo 16K | Bhi 16K | Blo 16K = 64KB; 2 buffers.
#define OFF_AHI 0
#define OFF_ALO 16384
#define OFF_BHI 32768
#define OFF_BLO 49152
#define BUF_SZ  65536
#define DSMEM_TOTAL (2 * BUF_SZ + 128)

// ---------------------------------------------------------------------------
__device__ __forceinline__ uint32_t smem_u32(const void* p) {
    uint32_t a;
    asm("{ .reg .u64 t; cvta.to.shared.u64 t, %1; cvt.u32.u64 %0, t; }" : "=r"(a) : "l"(p));
    return a;
}
__device__ __forceinline__ void cpa16(uint32_t dst, const void* src) {
    asm volatile("cp.async.cg.shared.global [%0], [%1], 16;" :: "r"(dst), "l"(src));
}
#define CPA_COMMIT() asm volatile("cp.async.commit_group;" ::: "memory")

__device__ __forceinline__ void ldsm4(uint32_t* d, uint32_t addr) {
    asm volatile("ldmatrix.sync.aligned.m8n8.x4.shared.b16 {%0,%1,%2,%3}, [%4];"
                 : "=r"(d[0]), "=r"(d[1]), "=r"(d[2]), "=r"(d[3]) : "r"(addr));
}
__device__ __forceinline__ void mma16816(float* c, const uint32_t* a, const uint32_t* b) {
    asm volatile("mma.sync.aligned.m16n8k16.row.col.f32.bf16.bf16.f32 "
                 "{%0,%1,%2,%3}, {%4,%5,%6,%7}, {%8,%9}, {%0,%1,%2,%3};"
                 : "+f"(c[0]), "+f"(c[1]), "+f"(c[2]), "+f"(c[3])
                 : "r"(a[0]), "r"(a[1]), "r"(a[2]), "r"(a[3]), "r"(b[0]), "r"(b[1]));
}

// exp2 on the FMA pipe: float-bias range reduction + degree-5 Taylor on [-0.5,0.5].
__device__ __forceinline__ float fexp2(float s) {
    float z = s + 12582912.0f;            // 1.5*2^23: low mantissa bits = rint(s)
    float f = s - (z - 12582912.0f);      // frac in [-0.5, 0.5]
    int   k = __float_as_int(z) << 23;    // rint(s) << 23 (exponent adjust)
    float p =             1.3333558e-3f;
    p = fmaf(p, f, 9.6181291e-3f);
    p = fmaf(p, f, 5.5504109e-2f);
    p = fmaf(p, f, 2.4022651e-1f);
    p = fmaf(p, f, 6.9314718e-1f);
    p = fmaf(p, f, 1.0f);
    return __int_as_float(__float_as_int(p) + k);
}

// ---------------------------------------------------------------------------
// Kernel 1: normalize rows -> bf16 hi/lo split; zero accumulators.
// ---------------------------------------------------------------------------
__global__ void norm_kernel(const float* __restrict__ X) {
    int row  = blockIdx.x * 8 + (threadIdx.x >> 5);
    int lane = threadIdx.x & 31;
    const float4* x4 = reinterpret_cast<const float4*>(X + row * DDIM);
    float4 v1 = x4[lane];
    float4 v2 = x4[lane + 32];
    float ss = v1.x*v1.x + v1.y*v1.y + v1.z*v1.z + v1.w*v1.w
             + v2.x*v2.x + v2.y*v2.y + v2.z*v2.z + v2.w*v2.w;
    #pragma unroll
    for (int o = 16; o > 0; o >>= 1) ss += __shfl_xor_sync(0xffffffffu, ss, o);
    float r = rsqrtf(ss);
    float vs[8] = {v1.x*r, v1.y*r, v1.z*r, v1.w*r, v2.x*r, v2.y*r, v2.z*r, v2.w*r};

    __nv_bfloat162* yh = reinterpret_cast<__nv_bfloat162*>(g_Yhi + row * DDIM);
    __nv_bfloat162* yl = reinterpret_cast<__nv_bfloat162*>(g_Ylo + row * DDIM);
    #pragma unroll
    for (int p = 0; p < 4; p++) {
        float a = vs[p * 2], b = vs[p * 2 + 1];
        __nv_bfloat162 h = __floats2bfloat162_rn(a, b);
        float2 hf = __bfloat1622float2(h);
        __nv_bfloat162 l = __floats2bfloat162_rn(a - hf.x, b - hf.y);
        int base = (p < 2) ? (lane * 2 + p) : ((lane + 32) * 2 + (p - 2));
        yh[base] = h;
        yl[base] = l;
    }
    if (lane == 0) { g_tot[row] = 0.0f; g_pos[row] = 0.0f; }
}

// ---------------------------------------------------------------------------
// Kernel 2: bf16 hi/lo HMMA GEMM (mma.sync) + fused exp epilogue.
// 8 warps: 2 (M) x 4 (N); warp tile 64x32; K pipelined in 64-elem chunks.
// ---------------------------------------------------------------------------
__global__ __launch_bounds__(256, 1)
void gemm_mma_kernel(const int* __restrict__ labels, const float* __restrict__ tptr) {
    extern __shared__ char dsm_raw[];
    __shared__ int lc[TN];

    const int tid  = threadIdx.x;
    const int wid  = tid >> 5;
    const int lane = tid & 31;
    const int row0 = blockIdx.y * TM;
    const int col0 = blockIdx.x * TN;
    const uint32_t sbase = (smem_u32(dsm_raw) + 127u) & ~127u;

    if (tid < TN) lc[tid] = labels[col0 + tid];

    const char* hiP = (const char*)g_Yhi;
    const char* loP = (const char*)g_Ylo;

    // ---- cp.async chunk loader: 16 x 16B per thread ----
    auto load_chunk = [&](int buf, int kc) {
        uint32_t b = sbase + buf * BUF_SZ;
        #pragma unroll
        for (int i = 0; i < 4; i++) {
            int idx = tid + i * 256;
            int r = idx >> 3, u = idx & 7;
            uint32_t dof = r * 128 + ((u ^ (r & 7)) << 4);
            size_t gs = (size_t)(row0 + r) * (DDIM * 2) + kc * 128 + u * 16;
            cpa16(b + OFF_AHI + dof, hiP + gs);
            cpa16(b + OFF_ALO + dof, loP + gs);
        }
        #pragma unroll
        for (int i = 0; i < 4; i++) {
            int idx = tid + i * 256;
            int r = idx >> 3, u = idx & 7;
            uint32_t dof = r * 128 + ((u ^ (r & 7)) << 4);
            size_t gs = (size_t)(col0 + r) * (DDIM * 2) + kc * 128 + u * 16;
            cpa16(b + OFF_BHI + dof, hiP + gs);
            cpa16(b + OFF_BLO + dof, loP + gs);
        }
    };

    float acc[4][4][4];
    #pragma unroll
    for (int m = 0; m < 4; m++)
        #pragma unroll
        for (int n = 0; n < 4; n++)
            #pragma unroll
            for (int j = 0; j < 4; j++) acc[m][n][j] = 0.0f;

    const int wm = wid & 1, wn = wid >> 1;
    const int sub = lane >> 3, l7 = lane & 7;

    load_chunk(0, 0);
    CPA_COMMIT();

    const int NCH = DDIM / KCH;  // 4
    #pragma unroll 1
    for (int kc = 0; kc < NCH; kc++) {
        if (kc < NCH - 1) {
            load_chunk((kc + 1) & 1, kc + 1);
            CPA_COMMIT();
            asm volatile("cp.async.wait_group 1;" ::: "memory");
        } else {
            asm volatile("cp.async.wait_group 0;" ::: "memory");
        }
        __syncthreads();

        const uint32_t b = sbase + (kc & 1) * BUF_SZ;
        #pragma unroll
        for (int ks = 0; ks < 4; ks++) {
            uint32_t ah[4][4], al[4][4], bh[2][4], bl[2][4];
            #pragma unroll
            for (int ma = 0; ma < 4; ma++) {
                int mr = wm * 64 + ma * 16 + ((sub & 1) << 3) + l7;
                int u  = 2 * ks + (sub >> 1);
                uint32_t dof = mr * 128 + ((u ^ (mr & 7)) << 4);
                ldsm4(ah[ma], b + OFF_AHI + dof);
                ldsm4(al[ma], b + OFF_ALO + dof);
            }
            #pragma unroll
            for (int nb = 0; nb < 2; nb++) {
                int nr = wn * 32 + nb * 16 + ((sub >> 1) << 3) + l7;
                int u  = 2 * ks + (sub & 1);
                uint32_t dof = nr * 128 + ((u ^ (nr & 7)) << 4);
                ldsm4(bh[nb], b + OFF_BHI + dof);
                ldsm4(bl[nb], b + OFF_BLO + dof);
            }
            #pragma unroll
            for (int ma = 0; ma < 4; ma++)
                #pragma unroll
                for (int na = 0; na < 4; na++) {
                    const uint32_t* Bh = &bh[na >> 1][(na & 1) * 2];
                    const uint32_t* Bl = &bl[na >> 1][(na & 1) * 2];
                    mma16816(acc[ma][na], ah[ma], Bh);
                    mma16816(acc[ma][na], ah[ma], Bl);
                    mma16816(acc[ma][na], al[ma], Bh);
                }
        }
        __syncthreads();
    }

    // ---- Epilogue: e = exp2(cos*esc); tot += e; pos += (same label ? e : 1) ----
    const float esc = 1.442695041f / (*tptr);
    const int q = lane & 3, g = lane >> 2;

    int cl[4][2];
    #pragma unroll
    for (int na = 0; na < 4; na++) {
        cl[na][0] = lc[wn * 32 + na * 8 + q * 2];
        cl[na][1] = lc[wn * 32 + na * 8 + q * 2 + 1];
    }

    #pragma unroll
    for (int ma = 0; ma < 4; ma++) {
        int rA = row0 + wm * 64 + ma * 16 + g;
        int rB = rA + 8;
        int lA = labels[rA], lB = labels[rB];
        float tsA = 0.f, psA = 0.f, tsB = 0.f, psB = 0.f;
        #pragma unroll
        for (int na = 0; na < 4; na++) {
            float e0 = fexp2(acc[ma][na][0] * esc);
            float e1 = fexp2(acc[ma][na][1] * esc);
            float e2 = fexp2(acc[ma][na][2] * esc);
            float e3 = fexp2(acc[ma][na][3] * esc);
            tsA += e0 + e1;
            tsB += e2 + e3;
            psA += ((lA == cl[na][0]) ? e0 : 1.0f) + ((lA == cl[na][1]) ? e1 : 1.0f);
            psB += ((lB == cl[na][0]) ? e2 : 1.0f) + ((lB == cl[na][1]) ? e3 : 1.0f);
        }
        #pragma unroll
        for (int o = 1; o <= 2; o <<= 1) {
            tsA += __shfl_xor_sync(0xffffffffu, tsA, o);
            psA += __shfl_xor_sync(0xffffffffu, psA, o);
            tsB += __shfl_xor_sync(0xffffffffu, tsB, o);
            psB += __shfl_xor_sync(0xffffffffu, psB, o);
        }
        if (q == 0) {
            atomicAdd(&g_tot[rA], tsA);
            atomicAdd(&g_pos[rA], psA);
            atomicAdd(&g_tot[rB], tsB);
            atomicAdd(&g_pos[rB], psB);
        }
    }
}

// ---------------------------------------------------------------------------
// Kernel 3: loss = sum_i [log(tot_i + N - pos_i) - log(pos_i)] / N
// ---------------------------------------------------------------------------
__global__ void loss_kernel(float* __restrict__ out) {
    __shared__ double sd[256];
    double a = 0.0;
    for (int r = threadIdx.x; r < NROWS; r += 256) {
        float p  = g_pos[r];
        float ng = g_tot[r] + (float)NROWS - p;
        a += (double)(logf(ng) - logf(p));
    }
    sd[threadIdx.x] = a;
    __syncthreads();
    #pragma unroll
    for (int o = 128; o > 0; o >>= 1) {
        if (threadIdx.x < o) sd[threadIdx.x] += sd[threadIdx.x + o];
        __syncthreads();
    }
    if (threadIdx.x == 0) out[0] = (float)(sd[0] / (double)NROWS);
}

// ---------------------------------------------------------------------------
extern "C" void kernel_launch(void* const* d_in, const int* in_sizes, int n_in,
                              void* d_out, int out_size) {
    const float* X   = (const float*)d_in[0];
    const int*   lab = (const int*)d_in[1];
    const float* t   = (const float*)d_in[2];
    float*       out = (float*)d_out;

    cudaFuncSetAttribute(gemm_mma_kernel, cudaFuncAttributeMaxDynamicSharedMemorySize,
                         DSMEM_TOTAL);

    norm_kernel<<<NROWS / 8, 256>>>(X);
    dim3 grid(NROWS / TN, NROWS / TM);
    gemm_mma_kernel<<<grid, 256, DSMEM_TOTAL>>>(lab, t);
    loss_kernel<<<1, 256>>>(out);
}

// round 9
// speedup vs baseline: 3.8063x; 1.5599x over previous
#include <cuda_runtime.h>
#include <cuda_bf16.h>
#include <cstdint>

#define NROWS 8192
#define DDIM  256
#define TM    128
#define TN    128
#define KCH   64            // K chunk in bf16 elems = 128 bytes/row
#define NBLK  (NROWS / TM)  // 64 tile-blocks per side
#define NTILES (NBLK * (NBLK + 1) / 2)   // 2080 upper-triangular tiles

// Scratch (no cudaMalloc allowed).
__device__ __nv_bfloat16 g_Yhi[NROWS * DDIM];
__device__ __nv_bfloat16 g_Ylo[NROWS * DDIM];
__device__ float g_tot[NROWS];
__device__ float g_pos[NROWS];

// SMEM per buffer: Ahi 16K | Alo 16K | Bhi 16K | Blo 16K = 64KB; 2 buffers.
#define OFF_AHI 0
#define OFF_ALO 16384
#define OFF_BHI 32768
#define OFF_BLO 49152
#define BUF_SZ  65536
#define DSMEM_TOTAL (2 * BUF_SZ + 128)

// ---------------------------------------------------------------------------
__device__ __forceinline__ uint32_t smem_u32(const void* p) {
    uint32_t a;
    asm("{ .reg .u64 t; cvta.to.shared.u64 t, %1; cvt.u32.u64 %0, t; }" : "=r"(a) : "l"(p));
    return a;
}
__device__ __forceinline__ void cpa16(uint32_t dst, const void* src) {
    asm volatile("cp.async.cg.shared.global [%0], [%1], 16;" :: "r"(dst), "l"(src));
}
#define CPA_COMMIT() asm volatile("cp.async.commit_group;" ::: "memory")

__device__ __forceinline__ void ldsm4(uint32_t* d, uint32_t addr) {
    asm volatile("ldmatrix.sync.aligned.m8n8.x4.shared.b16 {%0,%1,%2,%3}, [%4];"
                 : "=r"(d[0]), "=r"(d[1]), "=r"(d[2]), "=r"(d[3]) : "r"(addr));
}
__device__ __forceinline__ void mma16816(float* c, const uint32_t* a, const uint32_t* b) {
    asm volatile("mma.sync.aligned.m16n8k16.row.col.f32.bf16.bf16.f32 "
                 "{%0,%1,%2,%3}, {%4,%5,%6,%7}, {%8,%9}, {%0,%1,%2,%3};"
                 : "+f"(c[0]), "+f"(c[1]), "+f"(c[2]), "+f"(c[3])
                 : "r"(a[0]), "r"(a[1]), "r"(a[2]), "r"(a[3]), "r"(b[0]), "r"(b[1]));
}

// exp2 on the FMA pipe: float-bias range reduction + degree-5 Taylor on [-0.5,0.5].
__device__ __forceinline__ float fexp2(float s) {
    float z = s + 12582912.0f;            // 1.5*2^23: low mantissa bits = rint(s)
    float f = s - (z - 12582912.0f);      // frac in [-0.5, 0.5]
    int   k = __float_as_int(z) << 23;    // rint(s) << 23 (exponent adjust)
    float p =             1.3333558e-3f;
    p = fmaf(p, f, 9.6181291e-3f);
    p = fmaf(p, f, 5.5504109e-2f);
    p = fmaf(p, f, 2.4022651e-1f);
    p = fmaf(p, f, 6.9314718e-1f);
    p = fmaf(p, f, 1.0f);
    return __int_as_float(__float_as_int(p) + k);
}

// ---------------------------------------------------------------------------
// Kernel 1: normalize rows -> bf16 hi/lo split; zero accumulators.
// ---------------------------------------------------------------------------
__global__ void norm_kernel(const float* __restrict__ X) {
    int row  = blockIdx.x * 8 + (threadIdx.x >> 5);
    int lane = threadIdx.x & 31;
    const float4* x4 = reinterpret_cast<const float4*>(X + row * DDIM);
    float4 v1 = x4[lane];
    float4 v2 = x4[lane + 32];
    float ss = v1.x*v1.x + v1.y*v1.y + v1.z*v1.z + v1.w*v1.w
             + v2.x*v2.x + v2.y*v2.y + v2.z*v2.z + v2.w*v2.w;
    #pragma unroll
    for (int o = 16; o > 0; o >>= 1) ss += __shfl_xor_sync(0xffffffffu, ss, o);
    float r = rsqrtf(ss);
    float vs[8] = {v1.x*r, v1.y*r, v1.z*r, v1.w*r, v2.x*r, v2.y*r, v2.z*r, v2.w*r};

    __nv_bfloat162* yh = reinterpret_cast<__nv_bfloat162*>(g_Yhi + row * DDIM);
    __nv_bfloat162* yl = reinterpret_cast<__nv_bfloat162*>(g_Ylo + row * DDIM);
    #pragma unroll
    for (int p = 0; p < 4; p++) {
        float a = vs[p * 2], b = vs[p * 2 + 1];
        __nv_bfloat162 h = __floats2bfloat162_rn(a, b);
        float2 hf = __bfloat1622float2(h);
        __nv_bfloat162 l = __floats2bfloat162_rn(a - hf.x, b - hf.y);
        int base = (p < 2) ? (lane * 2 + p) : ((lane + 32) * 2 + (p - 2));
        yh[base] = h;
        yl[base] = l;
    }
    if (lane == 0) { g_tot[row] = 0.0f; g_pos[row] = 0.0f; }
}

// ---------------------------------------------------------------------------
// Kernel 2: bf16 hi/lo HMMA GEMM on UPPER-TRIANGULAR tiles only.
// Off-diagonal tiles feed both row-side and (by symmetry) column-side sums.
// ---------------------------------------------------------------------------
__global__ __launch_bounds__(256, 1)
void gemm_mma_kernel(const int* __restrict__ labels, const float* __restrict__ tptr) {
    extern __shared__ char dsm_raw[];
    __shared__ int lc[TN];

    const int tid  = threadIdx.x;
    const int wid  = tid >> 5;
    const int lane = tid & 31;

    // ---- triangular tile decode: blockIdx.x -> (bi <= bj) ----
    const int k = blockIdx.x;
    int bi = (int)((2.0 * NBLK + 1.0
                    - sqrt((2.0 * NBLK + 1.0) * (2.0 * NBLK + 1.0) - 8.0 * (double)k)) * 0.5);
    while (bi > 0 && bi * NBLK - bi * (bi - 1) / 2 > k) bi--;
    while ((bi + 1) * NBLK - (bi + 1) * bi / 2 <= k) bi++;
    const int bj = bi + (k - (bi * NBLK - bi * (bi - 1) / 2));
    const int row0 = bi * TM;
    const int col0 = bj * TN;
    const bool offdiag = (bi != bj);

    const uint32_t sbase = (smem_u32(dsm_raw) + 127u) & ~127u;

    if (tid < TN) lc[tid] = labels[col0 + tid];

    const char* hiP = (const char*)g_Yhi;
    const char* loP = (const char*)g_Ylo;

    auto load_chunk = [&](int buf, int kc) {
        uint32_t b = sbase + buf * BUF_SZ;
        #pragma unroll
        for (int i = 0; i < 4; i++) {
            int idx = tid + i * 256;
            int r = idx >> 3, u = idx & 7;
            uint32_t dof = r * 128 + ((u ^ (r & 7)) << 4);
            size_t gs = (size_t)(row0 + r) * (DDIM * 2) + kc * 128 + u * 16;
            cpa16(b + OFF_AHI + dof, hiP + gs);
            cpa16(b + OFF_ALO + dof, loP + gs);
        }
        #pragma unroll
        for (int i = 0; i < 4; i++) {
            int idx = tid + i * 256;
            int r = idx >> 3, u = idx & 7;
            uint32_t dof = r * 128 + ((u ^ (r & 7)) << 4);
            size_t gs = (size_t)(col0 + r) * (DDIM * 2) + kc * 128 + u * 16;
            cpa16(b + OFF_BHI + dof, hiP + gs);
            cpa16(b + OFF_BLO + dof, loP + gs);
        }
    };

    float acc[4][4][4];
    #pragma unroll
    for (int m = 0; m < 4; m++)
        #pragma unroll
        for (int n = 0; n < 4; n++)
            #pragma unroll
            for (int j = 0; j < 4; j++) acc[m][n][j] = 0.0f;

    const int wm = wid & 1, wn = wid >> 1;
    const int sub = lane >> 3, l7 = lane & 7;

    load_chunk(0, 0);
    CPA_COMMIT();

    const int NCH = DDIM / KCH;  // 4
    #pragma unroll 1
    for (int kc = 0; kc < NCH; kc++) {
        if (kc < NCH - 1) {
            load_chunk((kc + 1) & 1, kc + 1);
            CPA_COMMIT();
            asm volatile("cp.async.wait_group 1;" ::: "memory");
        } else {
            asm volatile("cp.async.wait_group 0;" ::: "memory");
        }
        __syncthreads();

        const uint32_t b = sbase + (kc & 1) * BUF_SZ;
        #pragma unroll
        for (int ks = 0; ks < 4; ks++) {
            uint32_t ah[4][4], al[4][4], bh[2][4], bl[2][4];
            #pragma unroll
            for (int ma = 0; ma < 4; ma++) {
                int mr = wm * 64 + ma * 16 + ((sub & 1) << 3) + l7;
                int u  = 2 * ks + (sub >> 1);
                uint32_t dof = mr * 128 + ((u ^ (mr & 7)) << 4);
                ldsm4(ah[ma], b + OFF_AHI + dof);
                ldsm4(al[ma], b + OFF_ALO + dof);
            }
            #pragma unroll
            for (int nb = 0; nb < 2; nb++) {
                int nr = wn * 32 + nb * 16 + ((sub >> 1) << 3) + l7;
                int u  = 2 * ks + (sub & 1);
                uint32_t dof = nr * 128 + ((u ^ (nr & 7)) << 4);
                ldsm4(bh[nb], b + OFF_BHI + dof);
                ldsm4(bl[nb], b + OFF_BLO + dof);
            }
            #pragma unroll
            for (int ma = 0; ma < 4; ma++)
                #pragma unroll
                for (int na = 0; na < 4; na++) {
                    const uint32_t* Bh = &bh[na >> 1][(na & 1) * 2];
                    const uint32_t* Bl = &bl[na >> 1][(na & 1) * 2];
                    mma16816(acc[ma][na], ah[ma], Bh);
                    mma16816(acc[ma][na], ah[ma], Bl);
                    mma16816(acc[ma][na], al[ma], Bh);
                }
        }
        __syncthreads();
    }

    // ---- Epilogue ----
    const float esc = 1.442695041f / (*tptr);
    const int q = lane & 3, g = lane >> 2;

    int cl_[4][2];
    #pragma unroll
    for (int na = 0; na < 4; na++) {
        cl_[na][0] = lc[wn * 32 + na * 8 + q * 2];
        cl_[na][1] = lc[wn * 32 + na * 8 + q * 2 + 1];
    }

    float ct[4][2], cp[4][2];   // column-side accumulators (off-diag only)
    #pragma unroll
    for (int na = 0; na < 4; na++) { ct[na][0] = ct[na][1] = cp[na][0] = cp[na][1] = 0.f; }

    #pragma unroll
    for (int ma = 0; ma < 4; ma++) {
        int rA = row0 + wm * 64 + ma * 16 + g;
        int rB = rA + 8;
        int lA = labels[rA], lB = labels[rB];
        float tsA = 0.f, psA = 0.f, tsB = 0.f, psB = 0.f;
        #pragma unroll
        for (int na = 0; na < 4; na++) {
            float e0 = fexp2(acc[ma][na][0] * esc);
            float e1 = fexp2(acc[ma][na][1] * esc);
            float e2 = fexp2(acc[ma][na][2] * esc);
            float e3 = fexp2(acc[ma][na][3] * esc);
            bool m0 = (lA == cl_[na][0]), m1 = (lA == cl_[na][1]);
            bool m2 = (lB == cl_[na][0]), m3 = (lB == cl_[na][1]);
            tsA += e0 + e1;
            tsB += e2 + e3;
            psA += (m0 ? e0 : 1.0f) + (m1 ? e1 : 1.0f);
            psB += (m2 ? e2 : 1.0f) + (m3 ? e3 : 1.0f);
            if (offdiag) {
                ct[na][0] += e0 + e2;
                ct[na][1] += e1 + e3;
                cp[na][0] += (m0 ? e0 : 1.0f) + (m2 ? e2 : 1.0f);
                cp[na][1] += (m1 ? e1 : 1.0f) + (m3 ? e3 : 1.0f);
            }
        }
        #pragma unroll
        for (int o = 1; o <= 2; o <<= 1) {
            tsA += __shfl_xor_sync(0xffffffffu, tsA, o);
            psA += __shfl_xor_sync(0xffffffffu, psA, o);
            tsB += __shfl_xor_sync(0xffffffffu, tsB, o);
            psB += __shfl_xor_sync(0xffffffffu, psB, o);
        }
        if (q == 0) {
            atomicAdd(&g_tot[rA], tsA);
            atomicAdd(&g_pos[rA], psA);
            atomicAdd(&g_tot[rB], tsB);
            atomicAdd(&g_pos[rB], psB);
        }
    }

    if (offdiag) {
        // Reduce column sums over the 8 row-groups (lanes differing in g).
        #pragma unroll
        for (int na = 0; na < 4; na++)
            #pragma unroll
            for (int bb = 0; bb < 2; bb++) {
                float t = ct[na][bb], p = cp[na][bb];
                #pragma unroll
                for (int o = 4; o <= 16; o <<= 1) {
                    t += __shfl_xor_sync(0xffffffffu, t, o);
                    p += __shfl_xor_sync(0xffffffffu, p, o);
                }
                if (g == 0) {
                    int col = col0 + wn * 32 + na * 8 + q * 2 + bb;
                    atomicAdd(&g_tot[col], t);
                    atomicAdd(&g_pos[col], p);
                }
            }
    }
}

// ---------------------------------------------------------------------------
// Kernel 3: loss = sum_i [log(tot_i + N - pos_i) - log(pos_i)] / N
// ---------------------------------------------------------------------------
__global__ void loss_kernel(float* __restrict__ out) {
    __shared__ double sd[256];
    double a = 0.0;
    for (int r = threadIdx.x; r < NROWS; r += 256) {
        float p  = g_pos[r];
        float ng = g_tot[r] + (float)NROWS - p;
        a += (double)(logf(ng) - logf(p));
    }
    sd[threadIdx.x] = a;
    __syncthreads();
    #pragma unroll
    for (int o = 128; o > 0; o >>= 1) {
        if (threadIdx.x < o) sd[threadIdx.x] += sd[threadIdx.x + o];
        __syncthreads();
    }
    if (threadIdx.x == 0) out[0] = (float)(sd[0] / (double)NROWS);
}

// ---------------------------------------------------------------------------
extern "C" void kernel_launch(void* const* d_in, const int* in_sizes, int n_in,
                              void* d_out, int out_size) {
    const float* X   = (const float*)d_in[0];
    const int*   lab = (const int*)d_in[1];
    const float* t   = (const float*)d_in[2];
    float*       out = (float*)d_out;

    cudaFuncSetAttribute(gemm_mma_kernel, cudaFuncAttributeMaxDynamicSharedMemorySize,
                         DSMEM_TOTAL);

    norm_kernel<<<NROWS / 8, 256>>>(X);
    gemm_mma_kernel<<<NTILES, 256, DSMEM_TOTAL>>>(lab, t);
    loss_kernel<<<1, 256>>>(out);
}

// round 10
// speedup vs baseline: 4.3859x; 1.1523x over previous
#include <cuda_runtime.h>
#include <cuda_bf16.h>
#include <cstdint>

#define NROWS 8192
#define DDIM  256
#define TM    128
#define TN    128
#define KCH   32            // K chunk in bf16 elems = 64 bytes/row
#define NBLK  (NROWS / TM)
#define NTILES (NBLK * (NBLK + 1) / 2)   // 2080 upper-triangular tiles

// Scratch (no cudaMalloc allowed).
__device__ __nv_bfloat16 g_Yhi[NROWS * DDIM];
__device__ __nv_bfloat16 g_Ylo[NROWS * DDIM];
__device__ float g_tot[NROWS];
__device__ float g_pos[NROWS];

// SMEM per buffer: Ahi 8K | Alo 8K | Bhi 8K | Blo 8K = 32KB; 2 buffers = 64KB.
#define OFF_AHI 0
#define OFF_ALO 8192
#define OFF_BHI 16384
#define OFF_BLO 24576
#define BUF_SZ  32768
#define DSMEM_TOTAL (2 * BUF_SZ + 128)

// ---------------------------------------------------------------------------
__device__ __forceinline__ uint32_t smem_u32(const void* p) {
    uint32_t a;
    asm("{ .reg .u64 t; cvta.to.shared.u64 t, %1; cvt.u32.u64 %0, t; }" : "=r"(a) : "l"(p));
    return a;
}
__device__ __forceinline__ void cpa16(uint32_t dst, const void* src) {
    asm volatile("cp.async.cg.shared.global [%0], [%1], 16;" :: "r"(dst), "l"(src));
}
#define CPA_COMMIT() asm volatile("cp.async.commit_group;" ::: "memory")

__device__ __forceinline__ void ldsm4(uint32_t* d, uint32_t addr) {
    asm volatile("ldmatrix.sync.aligned.m8n8.x4.shared.b16 {%0,%1,%2,%3}, [%4];"
                 : "=r"(d[0]), "=r"(d[1]), "=r"(d[2]), "=r"(d[3]) : "r"(addr));
}
__device__ __forceinline__ void mma16816(float* c, const uint32_t* a, const uint32_t* b) {
    asm volatile("mma.sync.aligned.m16n8k16.row.col.f32.bf16.bf16.f32 "
                 "{%0,%1,%2,%3}, {%4,%5,%6,%7}, {%8,%9}, {%0,%1,%2,%3};"
                 : "+f"(c[0]), "+f"(c[1]), "+f"(c[2]), "+f"(c[3])
                 : "r"(a[0]), "r"(a[1]), "r"(a[2]), "r"(a[3]), "r"(b[0]), "r"(b[1]));
}

// 64B-row swizzle: unit x = u ^ ((r>>1)&3); (r%2, x) distinct across 8 rows.
__device__ __forceinline__ uint32_t dof64(int r, int u) {
    return (uint32_t)(r * 64 + ((u ^ ((r >> 1) & 3)) << 4));
}

// exp2 on the FMA pipe: float-bias range reduction + degree-5 Taylor on [-0.5,0.5].
__device__ __forceinline__ float fexp2(float s) {
    float z = s + 12582912.0f;
    float f = s - (z - 12582912.0f);
    int   k = __float_as_int(z) << 23;
    float p =             1.3333558e-3f;
    p = fmaf(p, f, 9.6181291e-3f);
    p = fmaf(p, f, 5.5504109e-2f);
    p = fmaf(p, f, 2.4022651e-1f);
    p = fmaf(p, f, 6.9314718e-1f);
    p = fmaf(p, f, 1.0f);
    return __int_as_float(__float_as_int(p) + k);
}

// ---------------------------------------------------------------------------
// Kernel 1: normalize rows -> bf16 hi/lo split; zero accumulators.
// ---------------------------------------------------------------------------
__global__ void norm_kernel(const float* __restrict__ X) {
    int row  = blockIdx.x * 8 + (threadIdx.x >> 5);
    int lane = threadIdx.x & 31;
    const float4* x4 = reinterpret_cast<const float4*>(X + row * DDIM);
    float4 v1 = x4[lane];
    float4 v2 = x4[lane + 32];
    float ss = v1.x*v1.x + v1.y*v1.y + v1.z*v1.z + v1.w*v1.w
             + v2.x*v2.x + v2.y*v2.y + v2.z*v2.z + v2.w*v2.w;
    #pragma unroll
    for (int o = 16; o > 0; o >>= 1) ss += __shfl_xor_sync(0xffffffffu, ss, o);
    float r = rsqrtf(ss);
    float vs[8] = {v1.x*r, v1.y*r, v1.z*r, v1.w*r, v2.x*r, v2.y*r, v2.z*r, v2.w*r};

    __nv_bfloat162* yh = reinterpret_cast<__nv_bfloat162*>(g_Yhi + row * DDIM);
    __nv_bfloat162* yl = reinterpret_cast<__nv_bfloat162*>(g_Ylo + row * DDIM);
    #pragma unroll
    for (int p = 0; p < 4; p++) {
        float a = vs[p * 2], b = vs[p * 2 + 1];
        __nv_bfloat162 h = __floats2bfloat162_rn(a, b);
        float2 hf = __bfloat1622float2(h);
        __nv_bfloat162 l = __floats2bfloat162_rn(a - hf.x, b - hf.y);
        int base = (p < 2) ? (lane * 2 + p) : ((lane + 32) * 2 + (p - 2));
        yh[base] = h;
        yl[base] = l;
    }
    if (lane == 0) { g_tot[row] = 0.0f; g_pos[row] = 0.0f; }
}

// ---------------------------------------------------------------------------
// Kernel 2: bf16 hi/lo HMMA GEMM on upper-triangular tiles, occupancy 2.
// ---------------------------------------------------------------------------
__global__ __launch_bounds__(256, 2)
void gemm_mma_kernel(const int* __restrict__ labels, const float* __restrict__ tptr) {
    extern __shared__ char dsm_raw[];
    __shared__ int lc[TN];

    const int tid  = threadIdx.x;
    const int wid  = tid >> 5;
    const int lane = tid & 31;

    // ---- triangular tile decode: blockIdx.x -> (bi <= bj) ----
    const int k = blockIdx.x;
    int bi = (int)((2.0 * NBLK + 1.0
                    - sqrt((2.0 * NBLK + 1.0) * (2.0 * NBLK + 1.0) - 8.0 * (double)k)) * 0.5);
    while (bi > 0 && bi * NBLK - bi * (bi - 1) / 2 > k) bi--;
    while ((bi + 1) * NBLK - (bi + 1) * bi / 2 <= k) bi++;
    const int bj = bi + (k - (bi * NBLK - bi * (bi - 1) / 2));
    const int row0 = bi * TM;
    const int col0 = bj * TN;
    const bool offdiag = (bi != bj);

    const uint32_t sbase = (smem_u32(dsm_raw) + 127u) & ~127u;

    if (tid < TN) lc[tid] = labels[col0 + tid];

    const char* hiP = (const char*)g_Yhi;
    const char* loP = (const char*)g_Ylo;

    // per chunk per tile: 128 rows x 4 units(16B); 512 units / 256 thr = 2 each.
    auto load_chunk = [&](int buf, int kc) {
        uint32_t b = sbase + buf * BUF_SZ;
        #pragma unroll
        for (int i = 0; i < 2; i++) {
            int idx = tid + i * 256;
            int r = idx >> 2, u = idx & 3;
            uint32_t dof = dof64(r, u);
            size_t gsA = (size_t)(row0 + r) * (DDIM * 2) + kc * 64 + u * 16;
            size_t gsB = (size_t)(col0 + r) * (DDIM * 2) + kc * 64 + u * 16;
            cpa16(b + OFF_AHI + dof, hiP + gsA);
            cpa16(b + OFF_ALO + dof, loP + gsA);
            cpa16(b + OFF_BHI + dof, hiP + gsB);
            cpa16(b + OFF_BLO + dof, loP + gsB);
        }
    };

    float acc[4][4][4];
    #pragma unroll
    for (int m = 0; m < 4; m++)
        #pragma unroll
        for (int n = 0; n < 4; n++)
            #pragma unroll
            for (int j = 0; j < 4; j++) acc[m][n][j] = 0.0f;

    const int wm = wid & 1, wn = wid >> 1;
    const int sub = lane >> 3, l7 = lane & 7;

    load_chunk(0, 0);
    CPA_COMMIT();

    const int NCH = DDIM / KCH;  // 8
    #pragma unroll 1
    for (int kc = 0; kc < NCH; kc++) {
        if (kc < NCH - 1) {
            load_chunk((kc + 1) & 1, kc + 1);
            CPA_COMMIT();
            asm volatile("cp.async.wait_group 1;" ::: "memory");
        } else {
            asm volatile("cp.async.wait_group 0;" ::: "memory");
        }
        __syncthreads();

        const uint32_t b = sbase + (kc & 1) * BUF_SZ;
        #pragma unroll
        for (int ks = 0; ks < 2; ks++) {
            uint32_t ah[4][4], al[4][4], bh[2][4], bl[2][4];
            #pragma unroll
            for (int ma = 0; ma < 4; ma++) {
                int mr = wm * 64 + ma * 16 + ((sub & 1) << 3) + l7;
                int u  = 2 * ks + (sub >> 1);
                uint32_t dof = dof64(mr, u);
                ldsm4(ah[ma], b + OFF_AHI + dof);
                ldsm4(al[ma], b + OFF_ALO + dof);
            }
            #pragma unroll
            for (int nb = 0; nb < 2; nb++) {
                int nr = wn * 32 + nb * 16 + ((sub >> 1) << 3) + l7;
                int u  = 2 * ks + (sub & 1);
                uint32_t dof = dof64(nr, u);
                ldsm4(bh[nb], b + OFF_BHI + dof);
                ldsm4(bl[nb], b + OFF_BLO + dof);
            }
            #pragma unroll
            for (int ma = 0; ma < 4; ma++)
                #pragma unroll
                for (int na = 0; na < 4; na++) {
                    const uint32_t* Bh = &bh[na >> 1][(na & 1) * 2];
                    const uint32_t* Bl = &bl[na >> 1][(na & 1) * 2];
                    mma16816(acc[ma][na], ah[ma], Bh);
                    mma16816(acc[ma][na], ah[ma], Bl);
                    mma16816(acc[ma][na], al[ma], Bh);
                }
        }
        __syncthreads();
    }

    // ---- Epilogue ----
    const float esc = 1.442695041f / (*tptr);
    const int q = lane & 3, g = lane >> 2;

    int cl_[4][2];
    #pragma unroll
    for (int na = 0; na < 4; na++) {
        cl_[na][0] = lc[wn * 32 + na * 8 + q * 2];
        cl_[na][1] = lc[wn * 32 + na * 8 + q * 2 + 1];
    }

    float ct[4][2], cp[4][2];   // column-side accumulators (off-diag only)
    #pragma unroll
    for (int na = 0; na < 4; na++) { ct[na][0] = ct[na][1] = cp[na][0] = cp[na][1] = 0.f; }

    #pragma unroll
    for (int ma = 0; ma < 4; ma++) {
        int rA = row0 + wm * 64 + ma * 16 + g;
        int rB = rA + 8;
        int lA = labels[rA], lB = labels[rB];
        float tsA = 0.f, psA = 0.f, tsB = 0.f, psB = 0.f;
        #pragma unroll
        for (int na = 0; na < 4; na++) {
            float e0 = fexp2(acc[ma][na][0] * esc);
            float e1 = fexp2(acc[ma][na][1] * esc);
            float e2 = fexp2(acc[ma][na][2] * esc);
            float e3 = fexp2(acc[ma][na][3] * esc);
            bool m0 = (lA == cl_[na][0]), m1 = (lA == cl_[na][1]);
            bool m2 = (lB == cl_[na][0]), m3 = (lB == cl_[na][1]);
            tsA += e0 + e1;
            tsB += e2 + e3;
            psA += (m0 ? e0 : 1.0f) + (m1 ? e1 : 1.0f);
            psB += (m2 ? e2 : 1.0f) + (m3 ? e3 : 1.0f);
            if (offdiag) {
                ct[na][0] += e0 + e2;
                ct[na][1] += e1 + e3;
                cp[na][0] += (m0 ? e0 : 1.0f) + (m2 ? e2 : 1.0f);
                cp[na][1] += (m1 ? e1 : 1.0f) + (m3 ? e3 : 1.0f);
            }
        }
        #pragma unroll
        for (int o = 1; o <= 2; o <<= 1) {
            tsA += __shfl_xor_sync(0xffffffffu, tsA, o);
            psA += __shfl_xor_sync(0xffffffffu, psA, o);
            tsB += __shfl_xor_sync(0xffffffffu, tsB, o);
            psB += __shfl_xor_sync(0xffffffffu, psB, o);
        }
        if (q == 0) {
            atomicAdd(&g_tot[rA], tsA);
            atomicAdd(&g_pos[rA], psA);
            atomicAdd(&g_tot[rB], tsB);
            atomicAdd(&g_pos[rB], psB);
        }
    }

    if (offdiag) {
        #pragma unroll
        for (int na = 0; na < 4; na++)
            #pragma unroll
            for (int bb = 0; bb < 2; bb++) {
                float t = ct[na][bb], p = cp[na][bb];
                #pragma unroll
                for (int o = 4; o <= 16; o <<= 1) {
                    t += __shfl_xor_sync(0xffffffffu, t, o);
                    p += __shfl_xor_sync(0xffffffffu, p, o);
                }
                if (g == 0) {
                    int col = col0 + wn * 32 + na * 8 + q * 2 + bb;
                    atomicAdd(&g_tot[col], t);
                    atomicAdd(&g_pos[col], p);
                }
            }
    }
}

// ---------------------------------------------------------------------------
// Kernel 3: loss = sum_i [log(tot_i + N - pos_i) - log(pos_i)] / N
// ---------------------------------------------------------------------------
__global__ void loss_kernel(float* __restrict__ out) {
    __shared__ double sd[256];
    double a = 0.0;
    for (int r = threadIdx.x; r < NROWS; r += 256) {
        float p  = g_pos[r];
        float ng = g_tot[r] + (float)NROWS - p;
        a += (double)(logf(ng) - logf(p));
    }
    sd[threadIdx.x] = a;
    __syncthreads();
    #pragma unroll
    for (int o = 128; o > 0; o >>= 1) {
        if (threadIdx.x < o) sd[threadIdx.x] += sd[threadIdx.x + o];
        __syncthreads();
    }
    if (threadIdx.x == 0) out[0] = (float)(sd[0] / (double)NROWS);
}

// ---------------------------------------------------------------------------
extern "C" void kernel_launch(void* const* d_in, const int* in_sizes, int n_in,
                              void* d_out, int out_size) {
    const float* X   = (const float*)d_in[0];
    const int*   lab = (const int*)d_in[1];
    const float* t   = (const float*)d_in[2];
    float*       out = (float*)d_out;

    cudaFuncSetAttribute(gemm_mma_kernel, cudaFuncAttributeMaxDynamicSharedMemorySize,
                         DSMEM_TOTAL);

    norm_kernel<<<NROWS / 8, 256>>>(X);
    gemm_mma_kernel<<<NTILES, 256, DSMEM_TOTAL>>>(lab, t);
    loss_kernel<<<1, 256>>>(out);
}

// round 12
// speedup vs baseline: 4.4369x; 1.0116x over previous
#include <cuda_runtime.h>
#include <cuda_bf16.h>
#include <cstdint>

#define NROWS 8192
#define DDIM  256
#define TM    128
#define TN    128
#define KCH   32            // K chunk in bf16 elems = 64 bytes/row
#define NBLK  (NROWS / TM)
#define NTILES (NBLK * (NBLK + 1) / 2)   // 2080 upper-triangular tiles

// Scratch (no cudaMalloc allowed).
__device__ __nv_bfloat16 g_Yhi[NROWS * DDIM];
__device__ __nv_bfloat16 g_Ylo[NROWS * DDIM];
__device__ float g_tot[NROWS];
__device__ float g_pos[NROWS];

// SMEM per buffer: Ahi 8K | Alo 8K | Bhi 8K | Blo 8K = 32KB; 3 buffers = 96KB.
#define OFF_AHI 0
#define OFF_ALO 8192
#define OFF_BHI 16384
#define OFF_BLO 24576
#define BUF_SZ  32768
#define NSTAGE  3
#define DSMEM_TOTAL (NSTAGE * BUF_SZ + 128)

// ---------------------------------------------------------------------------
__device__ __forceinline__ uint32_t smem_u32(const void* p) {
    uint32_t a;
    asm("{ .reg .u64 t; cvta.to.shared.u64 t, %1; cvt.u32.u64 %0, t; }" : "=r"(a) : "l"(p));
    return a;
}
__device__ __forceinline__ void cpa16(uint32_t dst, const void* src) {
    asm volatile("cp.async.cg.shared.global [%0], [%1], 16;" :: "r"(dst), "l"(src));
}
#define CPA_COMMIT() asm volatile("cp.async.commit_group;" ::: "memory")

__device__ __forceinline__ void ldsm4(uint32_t* d, uint32_t addr) {
    asm volatile("ldmatrix.sync.aligned.m8n8.x4.shared.b16 {%0,%1,%2,%3}, [%4];"
                 : "=r"(d[0]), "=r"(d[1]), "=r"(d[2]), "=r"(d[3]) : "r"(addr));
}
__device__ __forceinline__ void mma16816(float* c, const uint32_t* a, const uint32_t* b) {
    asm volatile("mma.sync.aligned.m16n8k16.row.col.f32.bf16.bf16.f32 "
                 "{%0,%1,%2,%3}, {%4,%5,%6,%7}, {%8,%9}, {%0,%1,%2,%3};"
                 : "+f"(c[0]), "+f"(c[1]), "+f"(c[2]), "+f"(c[3])
                 : "r"(a[0]), "r"(a[1]), "r"(a[2]), "r"(a[3]), "r"(b[0]), "r"(b[1]));
}

// 64B-row swizzle: unit x = u ^ ((r>>1)&3); (r%2, x) distinct across 8 rows.
__device__ __forceinline__ uint32_t dof64(int r, int u) {
    return (uint32_t)(r * 64 + ((u ^ ((r >> 1) & 3)) << 4));
}

// exp2 on the FMA pipe: float-bias range reduction + degree-5 Taylor on [-0.5,0.5].
__device__ __forceinline__ float fexp2(float s) {
    float z = s + 12582912.0f;
    float f = s - (z - 12582912.0f);
    int   k = __float_as_int(z) << 23;
    float p =             1.3333558e-3f;
    p = fmaf(p, f, 9.6181291e-3f);
    p = fmaf(p, f, 5.5504109e-2f);
    p = fmaf(p, f, 2.4022651e-1f);
    p = fmaf(p, f, 6.9314718e-1f);
    p = fmaf(p, f, 1.0f);
    return __int_as_float(__float_as_int(p) + k);
}

// ---------------------------------------------------------------------------
// Kernel 1: normalize rows -> bf16 hi/lo split; zero accumulators.
// ---------------------------------------------------------------------------
__global__ void norm_kernel(const float* __restrict__ X) {
    int row  = blockIdx.x * 8 + (threadIdx.x >> 5);
    int lane = threadIdx.x & 31;
    const float4* x4 = reinterpret_cast<const float4*>(X + row * DDIM);
    float4 v1 = x4[lane];
    float4 v2 = x4[lane + 32];
    float ss = v1.x*v1.x + v1.y*v1.y + v1.z*v1.z + v1.w*v1.w
             + v2.x*v2.x + v2.y*v2.y + v2.z*v2.z + v2.w*v2.w;
    #pragma unroll
    for (int o = 16; o > 0; o >>= 1) ss += __shfl_xor_sync(0xffffffffu, ss, o);
    float r = rsqrtf(ss);
    float vs[8] = {v1.x*r, v1.y*r, v1.z*r, v1.w*r, v2.x*r, v2.y*r, v2.z*r, v2.w*r};

    __nv_bfloat162* yh = reinterpret_cast<__nv_bfloat162*>(g_Yhi + row * DDIM);
    __nv_bfloat162* yl = reinterpret_cast<__nv_bfloat162*>(g_Ylo + row * DDIM);
    #pragma unroll
    for (int p = 0; p < 4; p++) {
        float a = vs[p * 2], b = vs[p * 2 + 1];
        __nv_bfloat162 h = __floats2bfloat162_rn(a, b);
        float2 hf = __bfloat1622float2(h);
        __nv_bfloat162 l = __floats2bfloat162_rn(a - hf.x, b - hf.y);
        int base = (p < 2) ? (lane * 2 + p) : ((lane + 32) * 2 + (p - 2));
        yh[base] = h;
        yl[base] = l;
    }
    if (lane == 0) { g_tot[row] = 0.0f; g_pos[row] = 0.0f; }
}

// ---------------------------------------------------------------------------
// Kernel 2: bf16 hi/lo HMMA GEMM on upper-triangular tiles, occ 2, 3-stage.
// ---------------------------------------------------------------------------
__global__ __launch_bounds__(256, 2)
void gemm_mma_kernel(const int* __restrict__ labels, const float* __restrict__ tptr) {
    extern __shared__ char dsm_raw[];
    __shared__ int lc[TN];

    const int tid  = threadIdx.x;
    const int wid  = tid >> 5;
    const int lane = tid & 31;

    // ---- triangular tile decode: blockIdx.x -> (bi <= bj) ----
    const int k = blockIdx.x;
    int bi = (int)((2.0 * NBLK + 1.0
                    - sqrt((2.0 * NBLK + 1.0) * (2.0 * NBLK + 1.0) - 8.0 * (double)k)) * 0.5);
    while (bi > 0 && bi * NBLK - bi * (bi - 1) / 2 > k) bi--;
    while ((bi + 1) * NBLK - (bi + 1) * bi / 2 <= k) bi++;
    const int bj = bi + (k - (bi * NBLK - bi * (bi - 1) / 2));
    const int row0 = bi * TM;
    const int col0 = bj * TN;
    const bool offdiag = (bi != bj);

    const uint32_t sbase = (smem_u32(dsm_raw) + 127u) & ~127u;

    if (tid < TN) lc[tid] = labels[col0 + tid];

    const char* hiP = (const char*)g_Yhi;
    const char* loP = (const char*)g_Ylo;

    // per chunk per tile: 128 rows x 4 units(16B); 512 units / 256 thr = 2 each.
    auto load_chunk = [&](int buf, int kc) {
        uint32_t b = sbase + buf * BUF_SZ;
        #pragma unroll
        for (int i = 0; i < 2; i++) {
            int idx = tid + i * 256;
            int r = idx >> 2, u = idx & 3;
            uint32_t dof = dof64(r, u);
            size_t gsA = (size_t)(row0 + r) * (DDIM * 2) + kc * 64 + u * 16;
            size_t gsB = (size_t)(col0 + r) * (DDIM * 2) + kc * 64 + u * 16;
            cpa16(b + OFF_AHI + dof, hiP + gsA);
            cpa16(b + OFF_ALO + dof, loP + gsA);
            cpa16(b + OFF_BHI + dof, hiP + gsB);
            cpa16(b + OFF_BLO + dof, loP + gsB);
        }
    };

    float acc[4][4][4];
    #pragma unroll
    for (int m = 0; m < 4; m++)
        #pragma unroll
        for (int n = 0; n < 4; n++)
            #pragma unroll
            for (int j = 0; j < 4; j++) acc[m][n][j] = 0.0f;

    const int wm = wid & 1, wn = wid >> 1;
    const int sub = lane >> 3, l7 = lane & 7;

    load_chunk(0, 0);
    CPA_COMMIT();
    load_chunk(1, 1);
    CPA_COMMIT();

    const int NCH = DDIM / KCH;  // 8
    int buf = 0;
    #pragma unroll 1
    for (int kc = 0; kc < NCH; kc++) {
        // Chunk kc ready? (kc+1 may still be in flight.)
        if (kc < NCH - 1) {
            asm volatile("cp.async.wait_group 1;" ::: "memory");
        } else {
            asm volatile("cp.async.wait_group 0;" ::: "memory");
        }
        // One barrier: data visible to all AND everyone done reading buf (kc-1)%3.
        __syncthreads();

        // Prefetch chunk kc+2 into the buffer freed by chunk kc-1.
        if (kc + 2 < NCH) {
            load_chunk((buf + 2) % NSTAGE, kc + 2);
            CPA_COMMIT();
        }

        const uint32_t b = sbase + buf * BUF_SZ;
        #pragma unroll
        for (int ks = 0; ks < 2; ks++) {
            uint32_t ah[4][4], al[4][4], bh[2][4], bl[2][4];
            #pragma unroll
            for (int ma = 0; ma < 4; ma++) {
                int mr = wm * 64 + ma * 16 + ((sub & 1) << 3) + l7;
                int u  = 2 * ks + (sub >> 1);
                uint32_t dof = dof64(mr, u);
                ldsm4(ah[ma], b + OFF_AHI + dof);
                ldsm4(al[ma], b + OFF_ALO + dof);
            }
            #pragma unroll
            for (int nb = 0; nb < 2; nb++) {
                int nr = wn * 32 + nb * 16 + ((sub >> 1) << 3) + l7;
                int u  = 2 * ks + (sub & 1);
                uint32_t dof = dof64(nr, u);
                ldsm4(bh[nb], b + OFF_BHI + dof);
                ldsm4(bl[nb], b + OFF_BLO + dof);
            }
            #pragma unroll
            for (int ma = 0; ma < 4; ma++)
                #pragma unroll
                for (int na = 0; na < 4; na++) {
                    const uint32_t* Bh = &bh[na >> 1][(na & 1) * 2];
                    const uint32_t* Bl = &bl[na >> 1][(na & 1) * 2];
                    mma16816(acc[ma][na], ah[ma], Bh);
                    mma16816(acc[ma][na], ah[ma], Bl);
                    mma16816(acc[ma][na], al[ma], Bh);
                }
        }
        buf = (buf + 1) % NSTAGE;
    }

    // ---- Epilogue ----
    const float esc = 1.442695041f / (*tptr);
    const int q = lane & 3, g = lane >> 2;

    int cl_[4][2];
    #pragma unroll
    for (int na = 0; na < 4; na++) {
        cl_[na][0] = lc[wn * 32 + na * 8 + q * 2];
        cl_[na][1] = lc[wn * 32 + na * 8 + q * 2 + 1];
    }

    float ct[4][2], cp[4][2];   // column-side accumulators (off-diag only)
    #pragma unroll
    for (int na = 0; na < 4; na++) { ct[na][0] = ct[na][1] = cp[na][0] = cp[na][1] = 0.f; }

    #pragma unroll
    for (int ma = 0; ma < 4; ma++) {
        int rA = row0 + wm * 64 + ma * 16 + g;
        int rB = rA + 8;
        int lA = labels[rA], lB = labels[rB];
        float tsA = 0.f, psA = 0.f, tsB = 0.f, psB = 0.f;
        #pragma unroll
        for (int na = 0; na < 4; na++) {
            float e0 = fexp2(acc[ma][na][0] * esc);
            float e1 = fexp2(acc[ma][na][1] * esc);
            float e2 = fexp2(acc[ma][na][2] * esc);
            float e3 = fexp2(acc[ma][na][3] * esc);
            bool m0 = (lA == cl_[na][0]), m1 = (lA == cl_[na][1]);
            bool m2 = (lB == cl_[na][0]), m3 = (lB == cl_[na][1]);
            tsA += e0 + e1;
            tsB += e2 + e3;
            psA += (m0 ? e0 : 1.0f) + (m1 ? e1 : 1.0f);
            psB += (m2 ? e2 : 1.0f) + (m3 ? e3 : 1.0f);
            if (offdiag) {
                ct[na][0] += e0 + e2;
                ct[na][1] += e1 + e3;
                cp[na][0] += (m0 ? e0 : 1.0f) + (m2 ? e2 : 1.0f);
                cp[na][1] += (m1 ? e1 : 1.0f) + (m3 ? e3 : 1.0f);
            }
        }
        #pragma unroll
        for (int o = 1; o <= 2; o <<= 1) {
            tsA += __shfl_xor_sync(0xffffffffu, tsA, o);
            psA += __shfl_xor_sync(0xffffffffu, psA, o);
            tsB += __shfl_xor_sync(0xffffffffu, tsB, o);
            psB += __shfl_xor_sync(0xffffffffu, psB, o);
        }
        if (q == 0) {
            atomicAdd(&g_tot[rA], tsA);
            atomicAdd(&g_pos[rA], psA);
            atomicAdd(&g_tot[rB], tsB);
            atomicAdd(&g_pos[rB], psB);
        }
    }

    if (offdiag) {
        #pragma unroll
        for (int na = 0; na < 4; na++)
            #pragma unroll
            for (int bb = 0; bb < 2; bb++) {
                float t = ct[na][bb], p = cp[na][bb];
                #pragma unroll
                for (int o = 4; o <= 16; o <<= 1) {
                    t += __shfl_xor_sync(0xffffffffu, t, o);
                    p += __shfl_xor_sync(0xffffffffu, p, o);
                }
                if (g == 0) {
                    int col = col0 + wn * 32 + na * 8 + q * 2 + bb;
                    atomicAdd(&g_tot[col], t);
                    atomicAdd(&g_pos[col], p);
                }
            }
    }
}

// ---------------------------------------------------------------------------
// Kernel 3: loss = sum_i [log(tot_i + N - pos_i) - log(pos_i)] / N
// ---------------------------------------------------------------------------
__global__ void loss_kernel(float* __restrict__ out) {
    __shared__ double sd[256];
    double a = 0.0;
    for (int r = threadIdx.x; r < NROWS; r += 256) {
        float p  = g_pos[r];
        float ng = g_tot[r] + (float)NROWS - p;
        a += (double)(logf(ng) - logf(p));
    }
    sd[threadIdx.x] = a;
    __syncthreads();
    #pragma unroll
    for (int o = 128; o > 0; o >>= 1) {
        if (threadIdx.x < o) sd[threadIdx.x] += sd[threadIdx.x + o];
        __syncthreads();
    }
    if (threadIdx.x == 0) out[0] = (float)(sd[0] / (double)NROWS);
}

// ---------------------------------------------------------------------------
extern "C" void kernel_launch(void* const* d_in, const int* in_sizes, int n_in,
                              void* d_out, int out_size) {
    const float* X   = (const float*)d_in[0];
    const int*   lab = (const int*)d_in[1];
    const float* t   = (const float*)d_in[2];
    float*       out = (float*)d_out;

    cudaFuncSetAttribute(gemm_mma_kernel, cudaFuncAttributeMaxDynamicSharedMemorySize,
                         DSMEM_TOTAL);

    norm_kernel<<<NROWS / 8, 256>>>(X);
    gemm_mma_kernel<<<NTILES, 256, DSMEM_TOTAL>>>(lab, t);
    loss_kernel<<<1, 256>>>(out);
}